// round 3
// baseline (speedup 1.0000x reference)
#include <cuda_runtime.h>

#define NODES_MAX 100000
#define D 128
#define DOUT 64
#define BN_EPS 1e-5f

// ---- scratch (static device globals; no allocation) ----
__device__ float g_h[(size_t)NODES_MAX * D];     // 51.2 MB  GEMM output
__device__ float g_agg[(size_t)NODES_MAX * D];   // 51.2 MB  scatter target
__device__ float g_colsum[D];
__device__ float g_colsumsq[D];
__device__ float g_scale[D];
__device__ float g_shift[D];
__device__ float g_deg[NODES_MAX];               // weighted out-degree
__device__ float g_v[D];                         // sum_n d_n * x1[n]

// ============================================================
// GEMM: H[n,m] = sum_k f(X[n,k]) * W[k,m], K = M = 128
// FUSE: f(x) = relu(scale_k * x + shift_k)  (BN+ReLU of previous layer)
// Block: 256 threads, 64 rows x 128 cols per block.
// ============================================================
template <bool FUSE>
__global__ __launch_bounds__(256) void gemm128_kernel(
    const float* __restrict__ X, const float* __restrict__ W,
    float* __restrict__ H, int nrows)
{
    extern __shared__ float sm[];
    float* ws = sm;          // [128][128]
    float* xs = sm + D * D;  // [64][128]
    const int tid = threadIdx.x;
    const int row0 = blockIdx.x * 64;

    // load W (128x128) into smem: 4096 float4, 16 per thread
    const float4* W4 = (const float4*)W;
    float4* ws4 = (float4*)ws;
#pragma unroll
    for (int i = 0; i < 16; i++)
        ws4[tid + 256 * i] = W4[tid + 256 * i];

    // load X tile (64x128), optionally applying BN affine + ReLU
    const int kr = tid & 31;   // float4 index within row
    const int rr = tid >> 5;   // 0..7
    float4 sc4, sh4;
    if (FUSE) {
        sc4 = ((const float4*)g_scale)[kr];
        sh4 = ((const float4*)g_shift)[kr];
    }
#pragma unroll
    for (int i = 0; i < 8; i++) {
        int r = rr + 8 * i;
        int grow = row0 + r;
        float4 v = make_float4(0.f, 0.f, 0.f, 0.f);
        if (grow < nrows) v = ((const float4*)X)[(size_t)grow * 32 + kr];
        if (FUSE) {
            v.x = fmaxf(fmaf(sc4.x, v.x, sh4.x), 0.f);
            v.y = fmaxf(fmaf(sc4.y, v.y, sh4.y), 0.f);
            v.z = fmaxf(fmaf(sc4.z, v.z, sh4.z), 0.f);
            v.w = fmaxf(fmaf(sc4.w, v.w, sh4.w), 0.f);
        }
        ((float4*)xs)[r * 32 + kr] = v;
    }
    __syncthreads();

    const int tr = tid >> 5;   // row group: rows tr*8 .. tr*8+7
    const int tc = tid & 31;   // col group: cols tc*4 .. tc*4+3
    float acc[8][4];
#pragma unroll
    for (int i = 0; i < 8; i++)
#pragma unroll
        for (int j = 0; j < 4; j++) acc[i][j] = 0.f;

#pragma unroll 2
    for (int k = 0; k < D; k += 4) {
        float4 w0 = ((const float4*)(ws + (k + 0) * D))[tc];
        float4 w1 = ((const float4*)(ws + (k + 1) * D))[tc];
        float4 w2 = ((const float4*)(ws + (k + 2) * D))[tc];
        float4 w3 = ((const float4*)(ws + (k + 3) * D))[tc];
#pragma unroll
        for (int i = 0; i < 8; i++) {
            float4 x4 = *((const float4*)(xs + (tr * 8 + i) * D + k));  // broadcast within warp
            acc[i][0] = fmaf(x4.x, w0.x, acc[i][0]);
            acc[i][1] = fmaf(x4.x, w0.y, acc[i][1]);
            acc[i][2] = fmaf(x4.x, w0.z, acc[i][2]);
            acc[i][3] = fmaf(x4.x, w0.w, acc[i][3]);
            acc[i][0] = fmaf(x4.y, w1.x, acc[i][0]);
            acc[i][1] = fmaf(x4.y, w1.y, acc[i][1]);
            acc[i][2] = fmaf(x4.y, w1.z, acc[i][2]);
            acc[i][3] = fmaf(x4.y, w1.w, acc[i][3]);
            acc[i][0] = fmaf(x4.z, w2.x, acc[i][0]);
            acc[i][1] = fmaf(x4.z, w2.y, acc[i][1]);
            acc[i][2] = fmaf(x4.z, w2.z, acc[i][2]);
            acc[i][3] = fmaf(x4.z, w2.w, acc[i][3]);
            acc[i][0] = fmaf(x4.w, w3.x, acc[i][0]);
            acc[i][1] = fmaf(x4.w, w3.y, acc[i][1]);
            acc[i][2] = fmaf(x4.w, w3.z, acc[i][2]);
            acc[i][3] = fmaf(x4.w, w3.w, acc[i][3]);
        }
    }

#pragma unroll
    for (int i = 0; i < 8; i++) {
        int grow = row0 + tr * 8 + i;
        if (grow < nrows)
            ((float4*)H)[(size_t)grow * 32 + tc] =
                make_float4(acc[i][0], acc[i][1], acc[i][2], acc[i][3]);
    }
}

// ============================================================
// Edge scatter: agg[dst] += w * h[src].  One warp per edge,
// one float4 per lane; vector reduction to L2 (no return).
// ============================================================
__global__ __launch_bounds__(256) void scatter_kernel(
    const float* __restrict__ H, const int* __restrict__ src,
    const int* __restrict__ dst, const float* __restrict__ wt,
    float* __restrict__ AGG, int E)
{
    int gid = blockIdx.x * 256 + threadIdx.x;
    int e = gid >> 5;
    if (e >= E) return;
    int lane = threadIdx.x & 31;
    int s = __ldg(src + e);
    int t = __ldg(dst + e);
    float w = __ldg(wt + e);
    float4 v = ((const float4*)H)[(size_t)s * 32 + lane];
    float4* p = (float4*)AGG + (size_t)t * 32 + lane;
    asm volatile("red.global.add.v4.f32 [%0], {%1,%2,%3,%4};"
                 :: "l"(p), "f"(v.x * w), "f"(v.y * w), "f"(v.z * w), "f"(v.w * w)
                 : "memory");
}

// ============================================================
// Column sums + sums of squares for BN statistics.
// Block: 256 threads = 8 row-lanes x 32 float4-column-groups.
// ============================================================
__global__ __launch_bounds__(256) void colstats_kernel(
    const float* __restrict__ AGG, int nrows)
{
    __shared__ float4 ssum[8][32];
    __shared__ float4 ssq[8][32];
    const int kr = threadIdx.x & 31;
    const int rr = threadIdx.x >> 5;
    float4 s = make_float4(0.f, 0.f, 0.f, 0.f);
    float4 q = make_float4(0.f, 0.f, 0.f, 0.f);
    for (int n = blockIdx.x * 8 + rr; n < nrows; n += gridDim.x * 8) {
        float4 v = ((const float4*)AGG)[(size_t)n * 32 + kr];
        s.x += v.x; s.y += v.y; s.z += v.z; s.w += v.w;
        q.x = fmaf(v.x, v.x, q.x);
        q.y = fmaf(v.y, v.y, q.y);
        q.z = fmaf(v.z, v.z, q.z);
        q.w = fmaf(v.w, v.w, q.w);
    }
    ssum[rr][kr] = s;
    ssq[rr][kr] = q;
    __syncthreads();
    if (rr == 0) {
#pragma unroll
        for (int i = 1; i < 8; i++) {
            float4 a = ssum[i][kr], b = ssq[i][kr];
            s.x += a.x; s.y += a.y; s.z += a.z; s.w += a.w;
            q.x += b.x; q.y += b.y; q.z += b.z; q.w += b.w;
        }
        float* ps = &g_colsum[4 * kr];
        float* pq = &g_colsumsq[4 * kr];
        asm volatile("red.global.add.v4.f32 [%0], {%1,%2,%3,%4};"
                     :: "l"(ps), "f"(s.x), "f"(s.y), "f"(s.z), "f"(s.w) : "memory");
        asm volatile("red.global.add.v4.f32 [%0], {%1,%2,%3,%4};"
                     :: "l"(pq), "f"(q.x), "f"(q.y), "f"(q.z), "f"(q.w) : "memory");
    }
}

// scale = gamma * rsqrt(var+eps); shift = beta - scale*mean.
// (conv bias b cancels inside BN, so it is not needed here)
__global__ void bnfinalize_kernel(const float* __restrict__ gamma,
                                  const float* __restrict__ beta, float inv_n)
{
    int c = threadIdx.x;
    float m = g_colsum[c] * inv_n;
    float var = fmaf(-m, m, g_colsumsq[c] * inv_n);
    float inv = rsqrtf(var + BN_EPS);
    float sc = gamma[c] * inv;
    g_scale[c] = sc;
    g_shift[c] = fmaf(-sc, m, beta[c]);
}

// weighted out-degree: deg[src] += w
__global__ void degscatter_kernel(const int* __restrict__ src,
                                  const float* __restrict__ wt, int E)
{
    int e = blockIdx.x * blockDim.x + threadIdx.x;
    if (e < E) atomicAdd(&g_deg[src[e]], wt[e]);
}

// v[c] = sum_n deg[n] * relu(scale_c * agg[n,c] + shift_c)
__global__ __launch_bounds__(256) void vreduce_kernel(
    const float* __restrict__ AGG, int nrows)
{
    __shared__ float4 ssum[8][32];
    const int kr = threadIdx.x & 31;
    const int rr = threadIdx.x >> 5;
    float4 sc4 = ((const float4*)g_scale)[kr];
    float4 sh4 = ((const float4*)g_shift)[kr];
    float4 acc = make_float4(0.f, 0.f, 0.f, 0.f);
    for (int n = blockIdx.x * 8 + rr; n < nrows; n += gridDim.x * 8) {
        float dn = g_deg[n];  // uniform within warp -> broadcast
        float4 a = ((const float4*)AGG)[(size_t)n * 32 + kr];
        float x0 = fmaxf(fmaf(sc4.x, a.x, sh4.x), 0.f);
        float x1 = fmaxf(fmaf(sc4.y, a.y, sh4.y), 0.f);
        float x2 = fmaxf(fmaf(sc4.z, a.z, sh4.z), 0.f);
        float x3 = fmaxf(fmaf(sc4.w, a.w, sh4.w), 0.f);
        acc.x = fmaf(dn, x0, acc.x);
        acc.y = fmaf(dn, x1, acc.y);
        acc.z = fmaf(dn, x2, acc.z);
        acc.w = fmaf(dn, x3, acc.w);
    }
    ssum[rr][kr] = acc;
    __syncthreads();
    if (rr == 0) {
#pragma unroll
        for (int i = 1; i < 8; i++) {
            float4 a = ssum[i][kr];
            acc.x += a.x; acc.y += a.y; acc.z += a.z; acc.w += a.w;
        }
        float* pv = &g_v[4 * kr];
        asm volatile("red.global.add.v4.f32 [%0], {%1,%2,%3,%4};"
                     :: "l"(pv), "f"(acc.x), "f"(acc.y), "f"(acc.z), "f"(acc.w) : "memory");
    }
}

// out[c] = sum_k v[k] * W2[k,c] + N * b2[c]   (64 outputs)
__global__ void final_kernel(const float* __restrict__ W2,
                             const float* __restrict__ b2,
                             float* __restrict__ out, float nf)
{
    int c = threadIdx.x;
    float s = 0.f;
#pragma unroll 8
    for (int k = 0; k < D; k++) s = fmaf(g_v[k], W2[k * DOUT + c], s);
    out[c] = fmaf(nf, b2[c], s);
}

// ============================================================

extern "C" void kernel_launch(void* const* d_in, const int* in_sizes, int n_in,
                              void* d_out, int out_size)
{
    const float* nf     = (const float*)d_in[0];
    const int*   ei     = (const int*)d_in[1];
    const float* ew     = (const float*)d_in[2];
    const float* W0     = (const float*)d_in[3];
    const float* W1     = (const float*)d_in[5];
    const float* W2     = (const float*)d_in[7];
    const float* b2     = (const float*)d_in[8];
    const float* gamma0 = (const float*)d_in[9];
    const float* beta0  = (const float*)d_in[10];
    const float* gamma1 = (const float*)d_in[11];
    const float* beta1  = (const float*)d_in[12];

    const int E = in_sizes[2];
    const int N = in_sizes[0] / D;
    const int* src = ei;
    const int* dst = ei + E;

    float *p_h, *p_agg, *p_cs, *p_cq, *p_deg, *p_v;
    cudaGetSymbolAddress((void**)&p_h, g_h);
    cudaGetSymbolAddress((void**)&p_agg, g_agg);
    cudaGetSymbolAddress((void**)&p_cs, g_colsum);
    cudaGetSymbolAddress((void**)&p_cq, g_colsumsq);
    cudaGetSymbolAddress((void**)&p_deg, g_deg);
    cudaGetSymbolAddress((void**)&p_v, g_v);

    const size_t smem = (size_t)(D * D + 64 * D) * sizeof(float);  // 96 KB
    cudaFuncSetAttribute((const void*)gemm128_kernel<false>,
                         cudaFuncAttributeMaxDynamicSharedMemorySize, (int)smem);
    cudaFuncSetAttribute((const void*)gemm128_kernel<true>,
                         cudaFuncAttributeMaxDynamicSharedMemorySize, (int)smem);

    const int gemm_blocks = (N + 63) / 64;
    const int sc_blocks = (E * 32 + 255) / 256;
    const int stat_blocks = 1184;

    // ---- init ----
    cudaMemsetAsync(p_agg, 0, (size_t)N * D * sizeof(float), 0);
    cudaMemsetAsync(p_cs, 0, D * sizeof(float), 0);
    cudaMemsetAsync(p_cq, 0, D * sizeof(float), 0);
    cudaMemsetAsync(p_deg, 0, (size_t)N * sizeof(float), 0);
    cudaMemsetAsync(p_v, 0, D * sizeof(float), 0);

    // ---- layer 0: h0 = nf @ W0 ; agg0 = scatter(h0) ; BN stats ----
    gemm128_kernel<false><<<gemm_blocks, 256, smem>>>(nf, W0, p_h, N);
    scatter_kernel<<<sc_blocks, 256>>>(p_h, src, dst, ew, p_agg, E);
    colstats_kernel<<<stat_blocks, 256>>>(p_agg, N);
    bnfinalize_kernel<<<1, D>>>(gamma0, beta0, 1.0f / (float)N);

    // ---- layer 1: h1 = relu(bn(agg0)) @ W1 ; agg1 = scatter(h1) ; BN stats ----
    gemm128_kernel<true><<<gemm_blocks, 256, smem>>>(p_agg, W1, p_h, N);
    cudaMemsetAsync(p_agg, 0, (size_t)N * D * sizeof(float), 0);
    cudaMemsetAsync(p_cs, 0, D * sizeof(float), 0);
    cudaMemsetAsync(p_cq, 0, D * sizeof(float), 0);
    scatter_kernel<<<sc_blocks, 256>>>(p_h, src, dst, ew, p_agg, E);
    colstats_kernel<<<stat_blocks, 256>>>(p_agg, N);
    bnfinalize_kernel<<<1, D>>>(gamma1, beta1, 1.0f / (float)N);

    // ---- layer 2 collapsed algebraically:
    // out = (sum_n deg[n] * relu(bn(agg1[n]))) @ W2 + N*b2
    degscatter_kernel<<<(E + 255) / 256, 256>>>(src, ew, E);
    vreduce_kernel<<<stat_blocks, 256>>>(p_agg, N);
    final_kernel<<<1, DOUT>>>(W2, b2, (float*)d_out, (float)N);
}

// round 7
// speedup vs baseline: 1.5180x; 1.5180x over previous
#include <cuda_runtime.h>

#define NODES_MAX 100000
#define EDGES_MAX 1600000
#define D 128
#define DOUT 64
#define BN_EPS 1e-5f
#define SCAN_CHUNK 1024
#define SCAN_NB ((NODES_MAX + SCAN_CHUNK - 1) / SCAN_CHUNK)

// ---- scratch (static device globals; no allocation) ----
__device__ float g_h[(size_t)NODES_MAX * D];     // 51.2 MB  GEMM output
__device__ float g_agg[(size_t)NODES_MAX * D];   // 51.2 MB  gather target
__device__ float g_colsum[D];
__device__ float g_colsumsq[D];
__device__ float g_scale[D];
__device__ float g_shift[D];
__device__ float g_deg[NODES_MAX];               // weighted out-degree
__device__ float g_v[D];                         // sum_n d_n * x1[n]
// CSR-by-dst
__device__ int  g_cnt[NODES_MAX];
__device__ int  g_rs[NODES_MAX + 1];
__device__ int  g_pos[NODES_MAX];
__device__ int  g_bsum[SCAN_NB + 1];
__device__ int  g_boff[SCAN_NB + 1];
__device__ int2 g_edges[EDGES_MAX];              // {src, bitcast(w)} sorted by dst

// ============================================================
// GEMM: H[n,m] = sum_k f(X[n,k]) * W[k,m], K = M = 128
// FUSE: f(x) = relu(scale_k * x + shift_k)  (BN+ReLU of previous layer)
// ============================================================
template <bool FUSE>
__global__ __launch_bounds__(256) void gemm128_kernel(
    const float* __restrict__ X, const float* __restrict__ W,
    float* __restrict__ H, int nrows)
{
    extern __shared__ float sm[];
    float* ws = sm;          // [128][128]
    float* xs = sm + D * D;  // [64][128]
    const int tid = threadIdx.x;
    const int row0 = blockIdx.x * 64;

    const float4* W4 = (const float4*)W;
    float4* ws4 = (float4*)ws;
#pragma unroll
    for (int i = 0; i < 16; i++)
        ws4[tid + 256 * i] = W4[tid + 256 * i];

    const int kr = tid & 31;
    const int rr = tid >> 5;
    float4 sc4, sh4;
    if (FUSE) {
        sc4 = ((const float4*)g_scale)[kr];
        sh4 = ((const float4*)g_shift)[kr];
    }
#pragma unroll
    for (int i = 0; i < 8; i++) {
        int r = rr + 8 * i;
        int grow = row0 + r;
        float4 v = make_float4(0.f, 0.f, 0.f, 0.f);
        if (grow < nrows) v = ((const float4*)X)[(size_t)grow * 32 + kr];
        if (FUSE) {
            v.x = fmaxf(fmaf(sc4.x, v.x, sh4.x), 0.f);
            v.y = fmaxf(fmaf(sc4.y, v.y, sh4.y), 0.f);
            v.z = fmaxf(fmaf(sc4.z, v.z, sh4.z), 0.f);
            v.w = fmaxf(fmaf(sc4.w, v.w, sh4.w), 0.f);
        }
        ((float4*)xs)[r * 32 + kr] = v;
    }
    __syncthreads();

    const int tr = tid >> 5;
    const int tc = tid & 31;
    float acc[8][4];
#pragma unroll
    for (int i = 0; i < 8; i++)
#pragma unroll
        for (int j = 0; j < 4; j++) acc[i][j] = 0.f;

#pragma unroll 2
    for (int k = 0; k < D; k += 4) {
        float4 w0 = ((const float4*)(ws + (k + 0) * D))[tc];
        float4 w1 = ((const float4*)(ws + (k + 1) * D))[tc];
        float4 w2 = ((const float4*)(ws + (k + 2) * D))[tc];
        float4 w3 = ((const float4*)(ws + (k + 3) * D))[tc];
#pragma unroll
        for (int i = 0; i < 8; i++) {
            float4 x4 = *((const float4*)(xs + (tr * 8 + i) * D + k));
            acc[i][0] = fmaf(x4.x, w0.x, acc[i][0]);
            acc[i][1] = fmaf(x4.x, w0.y, acc[i][1]);
            acc[i][2] = fmaf(x4.x, w0.z, acc[i][2]);
            acc[i][3] = fmaf(x4.x, w0.w, acc[i][3]);
            acc[i][0] = fmaf(x4.y, w1.x, acc[i][0]);
            acc[i][1] = fmaf(x4.y, w1.y, acc[i][1]);
            acc[i][2] = fmaf(x4.y, w1.z, acc[i][2]);
            acc[i][3] = fmaf(x4.y, w1.w, acc[i][3]);
            acc[i][0] = fmaf(x4.z, w2.x, acc[i][0]);
            acc[i][1] = fmaf(x4.z, w2.y, acc[i][1]);
            acc[i][2] = fmaf(x4.z, w2.z, acc[i][2]);
            acc[i][3] = fmaf(x4.z, w2.w, acc[i][3]);
            acc[i][0] = fmaf(x4.w, w3.x, acc[i][0]);
            acc[i][1] = fmaf(x4.w, w3.y, acc[i][1]);
            acc[i][2] = fmaf(x4.w, w3.z, acc[i][2]);
            acc[i][3] = fmaf(x4.w, w3.w, acc[i][3]);
        }
    }

#pragma unroll
    for (int i = 0; i < 8; i++) {
        int grow = row0 + tr * 8 + i;
        if (grow < nrows)
            ((float4*)H)[(size_t)grow * 32 + tc] =
                make_float4(acc[i][0], acc[i][1], acc[i][2], acc[i][3]);
    }
}

// ============================================================
// CSR build
// ============================================================
// histogram over dst + weighted out-degree over src (one edge pass)
__global__ void hist_deg_kernel(const int* __restrict__ src,
                                const int* __restrict__ dst,
                                const float* __restrict__ wt, int E)
{
    int e = blockIdx.x * blockDim.x + threadIdx.x;
    if (e >= E) return;
    atomicAdd(&g_cnt[dst[e]], 1);
    atomicAdd(&g_deg[src[e]], wt[e]);
}

// per-chunk sums
__global__ __launch_bounds__(256) void scan1_kernel(int nrows)
{
    __shared__ int wsum[8];
    int b = blockIdx.x, t = threadIdx.x;
    int base = b * SCAN_CHUNK + t * 4;
    int s = 0;
#pragma unroll
    for (int k = 0; k < 4; k++) {
        int idx = base + k;
        if (idx < nrows) s += g_cnt[idx];
    }
#pragma unroll
    for (int o = 16; o > 0; o >>= 1) s += __shfl_down_sync(0xffffffffu, s, o);
    if ((t & 31) == 0) wsum[t >> 5] = s;
    __syncthreads();
    if (t == 0) {
        int tot = 0;
#pragma unroll
        for (int i = 0; i < 8; i++) tot += wsum[i];
        g_bsum[b] = tot;
    }
}

// exclusive scan of chunk sums (small, serial) ; also writes rs[nrows]=E
__global__ void scan2_kernel(int nblocks, int nrows)
{
    if (threadIdx.x == 0) {
        int run = 0;
        for (int i = 0; i < nblocks; i++) {
            g_boff[i] = run;
            run += g_bsum[i];
        }
        g_rs[nrows] = run;
    }
}

// per-chunk exclusive scan -> row_start
__global__ __launch_bounds__(256) void scan3_kernel(int nrows)
{
    __shared__ int woff[8];
    int b = blockIdx.x, t = threadIdx.x;
    int base = b * SCAN_CHUNK + t * 4;
    int c[4];
    int s = 0;
#pragma unroll
    for (int k = 0; k < 4; k++) {
        int idx = base + k;
        c[k] = (idx < nrows) ? g_cnt[idx] : 0;
        s += c[k];
    }
    // warp inclusive scan of per-thread sums
    int incl = s;
#pragma unroll
    for (int o = 1; o < 32; o <<= 1) {
        int y = __shfl_up_sync(0xffffffffu, incl, o);
        if ((t & 31) >= o) incl += y;
    }
    if ((t & 31) == 31) woff[t >> 5] = incl;
    __syncthreads();
    if (t < 8) {
        int v = woff[t];
        int iv = v;
#pragma unroll
        for (int o = 1; o < 8; o <<= 1) {
            int y = __shfl_up_sync(0x000000ffu, iv, o);
            if (t >= o) iv += y;
        }
        woff[t] = iv - v;  // exclusive
    }
    __syncthreads();
    int excl = incl - s + woff[t >> 5] + g_boff[b];
#pragma unroll
    for (int k = 0; k < 4; k++) {
        int idx = base + k;
        if (idx < nrows) g_rs[idx] = excl;
        excl += c[k];
    }
}

// fill edges sorted by dst
__global__ void fill_kernel(const int* __restrict__ src,
                            const int* __restrict__ dst,
                            const float* __restrict__ wt, int E)
{
    int e = blockIdx.x * blockDim.x + threadIdx.x;
    if (e >= E) return;
    int slot = atomicAdd(&g_pos[dst[e]], 1);
    g_edges[slot] = make_int2(src[e], __float_as_int(wt[e]));
}

// ============================================================
// CSR gather: agg[n] = sum_{e: dst=n} w_e * h[src_e].  Warp per node.
// ============================================================
__global__ __launch_bounds__(256) void gather_kernel(
    const float* __restrict__ H, float* __restrict__ AGG, int nrows)
{
    int n = blockIdx.x * 8 + (threadIdx.x >> 5);
    if (n >= nrows) return;
    int lane = threadIdx.x & 31;
    int beg = g_rs[n], end = g_rs[n + 1];
    float4 acc = make_float4(0.f, 0.f, 0.f, 0.f);
    for (int base = beg; base < end; base += 32) {
        int m = min(32, end - base);
        int2 ed = make_int2(0, 0);
        if (lane < m) ed = g_edges[base + lane];
        for (int j = 0; j < m; j++) {
            int s = __shfl_sync(0xffffffffu, ed.x, j);
            float w = __int_as_float(__shfl_sync(0xffffffffu, ed.y, j));
            float4 v = ((const float4*)H)[(size_t)s * 32 + lane];
            acc.x = fmaf(w, v.x, acc.x);
            acc.y = fmaf(w, v.y, acc.y);
            acc.z = fmaf(w, v.z, acc.z);
            acc.w = fmaf(w, v.w, acc.w);
        }
    }
    ((float4*)AGG)[(size_t)n * 32 + lane] = acc;
}

// ============================================================
// Column sums + sums of squares for BN statistics.
// ============================================================
__global__ __launch_bounds__(256) void colstats_kernel(
    const float* __restrict__ AGG, int nrows)
{
    __shared__ float4 ssum[8][32];
    __shared__ float4 ssq[8][32];
    const int kr = threadIdx.x & 31;
    const int rr = threadIdx.x >> 5;
    float4 s = make_float4(0.f, 0.f, 0.f, 0.f);
    float4 q = make_float4(0.f, 0.f, 0.f, 0.f);
    for (int n = blockIdx.x * 8 + rr; n < nrows; n += gridDim.x * 8) {
        float4 v = ((const float4*)AGG)[(size_t)n * 32 + kr];
        s.x += v.x; s.y += v.y; s.z += v.z; s.w += v.w;
        q.x = fmaf(v.x, v.x, q.x);
        q.y = fmaf(v.y, v.y, q.y);
        q.z = fmaf(v.z, v.z, q.z);
        q.w = fmaf(v.w, v.w, q.w);
    }
    ssum[rr][kr] = s;
    ssq[rr][kr] = q;
    __syncthreads();
    if (rr == 0) {
#pragma unroll
        for (int i = 1; i < 8; i++) {
            float4 a = ssum[i][kr], b = ssq[i][kr];
            s.x += a.x; s.y += a.y; s.z += a.z; s.w += a.w;
            q.x += b.x; q.y += b.y; q.z += b.z; q.w += b.w;
        }
        float* ps = &g_colsum[4 * kr];
        float* pq = &g_colsumsq[4 * kr];
        asm volatile("red.global.add.v4.f32 [%0], {%1,%2,%3,%4};"
                     :: "l"(ps), "f"(s.x), "f"(s.y), "f"(s.z), "f"(s.w) : "memory");
        asm volatile("red.global.add.v4.f32 [%0], {%1,%2,%3,%4};"
                     :: "l"(pq), "f"(q.x), "f"(q.y), "f"(q.z), "f"(q.w) : "memory");
    }
}

__global__ void bnfinalize_kernel(const float* __restrict__ gamma,
                                  const float* __restrict__ beta, float inv_n)
{
    int c = threadIdx.x;
    float m = g_colsum[c] * inv_n;
    float var = fmaf(-m, m, g_colsumsq[c] * inv_n);
    float inv = rsqrtf(var + BN_EPS);
    float sc = gamma[c] * inv;
    g_scale[c] = sc;
    g_shift[c] = fmaf(-sc, m, beta[c]);
}

// v[c] = sum_n deg[n] * relu(scale_c * agg[n,c] + shift_c)
__global__ __launch_bounds__(256) void vreduce_kernel(
    const float* __restrict__ AGG, int nrows)
{
    __shared__ float4 ssum[8][32];
    const int kr = threadIdx.x & 31;
    const int rr = threadIdx.x >> 5;
    float4 sc4 = ((const float4*)g_scale)[kr];
    float4 sh4 = ((const float4*)g_shift)[kr];
    float4 acc = make_float4(0.f, 0.f, 0.f, 0.f);
    for (int n = blockIdx.x * 8 + rr; n < nrows; n += gridDim.x * 8) {
        float dn = g_deg[n];
        float4 a = ((const float4*)AGG)[(size_t)n * 32 + kr];
        float x0 = fmaxf(fmaf(sc4.x, a.x, sh4.x), 0.f);
        float x1 = fmaxf(fmaf(sc4.y, a.y, sh4.y), 0.f);
        float x2 = fmaxf(fmaf(sc4.z, a.z, sh4.z), 0.f);
        float x3 = fmaxf(fmaf(sc4.w, a.w, sh4.w), 0.f);
        acc.x = fmaf(dn, x0, acc.x);
        acc.y = fmaf(dn, x1, acc.y);
        acc.z = fmaf(dn, x2, acc.z);
        acc.w = fmaf(dn, x3, acc.w);
    }
    ssum[rr][kr] = acc;
    __syncthreads();
    if (rr == 0) {
#pragma unroll
        for (int i = 1; i < 8; i++) {
            float4 a = ssum[i][kr];
            acc.x += a.x; acc.y += a.y; acc.z += a.z; acc.w += a.w;
        }
        float* pv = &g_v[4 * kr];
        asm volatile("red.global.add.v4.f32 [%0], {%1,%2,%3,%4};"
                     :: "l"(pv), "f"(acc.x), "f"(acc.y), "f"(acc.z), "f"(acc.w) : "memory");
    }
}

__global__ void final_kernel(const float* __restrict__ W2,
                             const float* __restrict__ b2,
                             float* __restrict__ out, float nf)
{
    int c = threadIdx.x;
    float s = 0.f;
#pragma unroll 8
    for (int k = 0; k < D; k++) s = fmaf(g_v[k], W2[k * DOUT + c], s);
    out[c] = fmaf(nf, b2[c], s);
}

// ============================================================

extern "C" void kernel_launch(void* const* d_in, const int* in_sizes, int n_in,
                              void* d_out, int out_size)
{
    const float* nf     = (const float*)d_in[0];
    const int*   ei     = (const int*)d_in[1];
    const float* ew     = (const float*)d_in[2];
    const float* W0     = (const float*)d_in[3];
    const float* W1     = (const float*)d_in[5];
    const float* W2     = (const float*)d_in[7];
    const float* b2     = (const float*)d_in[8];
    const float* gamma0 = (const float*)d_in[9];
    const float* beta0  = (const float*)d_in[10];
    const float* gamma1 = (const float*)d_in[11];
    const float* beta1  = (const float*)d_in[12];

    const int E = in_sizes[2];
    const int N = in_sizes[0] / D;
    const int* src = ei;
    const int* dst = ei + E;

    float *p_h, *p_agg, *p_cs, *p_cq, *p_deg;
    float *p_v;
    int *p_cnt, *p_rs, *p_pos;
    cudaGetSymbolAddress((void**)&p_h, g_h);
    cudaGetSymbolAddress((void**)&p_agg, g_agg);
    cudaGetSymbolAddress((void**)&p_cs, g_colsum);
    cudaGetSymbolAddress((void**)&p_cq, g_colsumsq);
    cudaGetSymbolAddress((void**)&p_deg, g_deg);
    cudaGetSymbolAddress((void**)&p_v, g_v);
    cudaGetSymbolAddress((void**)&p_cnt, g_cnt);
    cudaGetSymbolAddress((void**)&p_rs, g_rs);
    cudaGetSymbolAddress((void**)&p_pos, g_pos);

    const size_t smem = (size_t)(D * D + 64 * D) * sizeof(float);  // 96 KB
    cudaFuncSetAttribute((const void*)gemm128_kernel<false>,
                         cudaFuncAttributeMaxDynamicSharedMemorySize, (int)smem);
    cudaFuncSetAttribute((const void*)gemm128_kernel<true>,
                         cudaFuncAttributeMaxDynamicSharedMemorySize, (int)smem);

    const int gemm_blocks = (N + 63) / 64;
    const int gather_blocks = (N + 7) / 8;
    const int stat_blocks = 1184;
    const int scan_blocks = (N + SCAN_CHUNK - 1) / SCAN_CHUNK;
    const int edge_blocks = (E + 255) / 256;

    // ---- init ----
    cudaMemsetAsync(p_cnt, 0, (size_t)N * sizeof(int), 0);
    cudaMemsetAsync(p_deg, 0, (size_t)N * sizeof(float), 0);
    cudaMemsetAsync(p_cs, 0, D * sizeof(float), 0);
    cudaMemsetAsync(p_cq, 0, D * sizeof(float), 0);
    cudaMemsetAsync(p_v, 0, D * sizeof(float), 0);

    // ---- CSR build (by dst) + weighted out-degree ----
    hist_deg_kernel<<<edge_blocks, 256>>>(src, dst, ew, E);
    scan1_kernel<<<scan_blocks, 256>>>(N);
    scan2_kernel<<<1, 32>>>(scan_blocks, N);
    scan3_kernel<<<scan_blocks, 256>>>(N);
    cudaMemcpyAsync(p_pos, p_rs, (size_t)N * sizeof(int),
                    cudaMemcpyDeviceToDevice, 0);
    fill_kernel<<<edge_blocks, 256>>>(src, dst, ew, E);

    // ---- layer 0 ----
    gemm128_kernel<false><<<gemm_blocks, 256, smem>>>(nf, W0, p_h, N);
    gather_kernel<<<gather_blocks, 256>>>(p_h, p_agg, N);
    colstats_kernel<<<stat_blocks, 256>>>(p_agg, N);
    bnfinalize_kernel<<<1, D>>>(gamma0, beta0, 1.0f / (float)N);

    // ---- layer 1 ----
    gemm128_kernel<true><<<gemm_blocks, 256, smem>>>(p_agg, W1, p_h, N);
    cudaMemsetAsync(p_cs, 0, D * sizeof(float), 0);
    cudaMemsetAsync(p_cq, 0, D * sizeof(float), 0);
    gather_kernel<<<gather_blocks, 256>>>(p_h, p_agg, N);
    colstats_kernel<<<stat_blocks, 256>>>(p_agg, N);
    bnfinalize_kernel<<<1, D>>>(gamma1, beta1, 1.0f / (float)N);

    // ---- layer 2 collapsed algebraically ----
    vreduce_kernel<<<stat_blocks, 256>>>(p_agg, N);
    final_kernel<<<1, DOUT>>>(W2, b2, (float*)d_out, (float)N);
}

// round 8
// speedup vs baseline: 1.9179x; 1.2634x over previous
#include <cuda_runtime.h>

#define NODES_MAX 100000
#define EDGES_MAX 1600000
#define D 128
#define DOUT 64
#define BN_EPS 1e-5f
#define SCAN_CHUNK 1024
#define SCAN_NB ((NODES_MAX + SCAN_CHUNK - 1) / SCAN_CHUNK)
#define SMP 132   // padded smem row stride (words)

// ---- scratch (static device globals; no allocation) ----
__device__ float g_h[(size_t)NODES_MAX * D];     // 51.2 MB  GEMM output
__device__ float g_agg[(size_t)NODES_MAX * D];   // 51.2 MB  gather target
__device__ float g_colsum[D];
__device__ float g_colsumsq[D];
__device__ float g_scale[D];
__device__ float g_shift[D];
__device__ float g_deg[NODES_MAX];               // weighted out-degree
__device__ float g_v[D];                         // sum_n d_n * x1[n]
// CSR-by-dst
__device__ int  g_cnt[NODES_MAX];
__device__ int  g_rs[NODES_MAX + 1];
__device__ int  g_pos[NODES_MAX];
__device__ int  g_bsum[SCAN_NB + 1];
__device__ int  g_boff[SCAN_NB + 1];
__device__ int2 g_edges[EDGES_MAX];              // {src, bitcast(w)} sorted by dst

__device__ __forceinline__ float to_tf32(float x) {
    unsigned u;
    asm("cvt.rna.tf32.f32 %0, %1;" : "=r"(u) : "f"(x));
    return __int_as_float(u);
}

// ============================================================
// TF32 tensor-core GEMM: H[n,m] = sum_k f(X[n,k]) * W[k,m]
// FUSE: f(x) = relu(scale_k * x + shift_k)  (BN+ReLU of previous layer)
// Block: 256 threads, 128x128 output tile; warp tile 32x64.
// ============================================================
template <bool FUSE>
__global__ __launch_bounds__(256) void gemm_tc_kernel(
    const float* __restrict__ X, const float* __restrict__ W,
    float* __restrict__ H, int nrows)
{
    extern __shared__ float sm[];
    float* xs = sm;             // [128][SMP]
    float* ws = sm + 128 * SMP; // [128][SMP]
    const int tid = threadIdx.x;
    const int row0 = blockIdx.x * 128;

    // ---- load W (128x128) -> smem (tf32-rounded, padded) ----
#pragma unroll
    for (int it = 0; it < 16; it++) {
        int i = tid + 256 * it;           // float4 index
        int r = i >> 5, c4 = i & 31;
        float4 v = ((const float4*)W)[r * 32 + c4];
        v.x = to_tf32(v.x); v.y = to_tf32(v.y);
        v.z = to_tf32(v.z); v.w = to_tf32(v.w);
        *(float4*)(ws + r * SMP + c4 * 4) = v;
    }

    // ---- load X tile (128x128) -> smem (BN+ReLU fused, tf32, padded) ----
    float4 sc4, sh4;
#pragma unroll
    for (int it = 0; it < 16; it++) {
        int i = tid + 256 * it;
        int r = i >> 5, c4 = i & 31;
        if (FUSE && it == 0) { /* nothing */ }
        float4 v = make_float4(0.f, 0.f, 0.f, 0.f);
        int grow = row0 + r;
        if (grow < nrows) v = ((const float4*)X)[(size_t)grow * 32 + c4];
        if (FUSE) {
            sc4 = ((const float4*)g_scale)[c4];
            sh4 = ((const float4*)g_shift)[c4];
            v.x = fmaxf(fmaf(sc4.x, v.x, sh4.x), 0.f);
            v.y = fmaxf(fmaf(sc4.y, v.y, sh4.y), 0.f);
            v.z = fmaxf(fmaf(sc4.z, v.z, sh4.z), 0.f);
            v.w = fmaxf(fmaf(sc4.w, v.w, sh4.w), 0.f);
        }
        v.x = to_tf32(v.x); v.y = to_tf32(v.y);
        v.z = to_tf32(v.z); v.w = to_tf32(v.w);
        *(float4*)(xs + r * SMP + c4 * 4) = v;
    }
    __syncthreads();

    const int warp = tid >> 5, lane = tid & 31;
    const int wr = warp >> 1, wc = warp & 1;   // warp tile: rows 32*wr, cols 64*wc
    const int qr = lane >> 2, qc = lane & 3;   // groupID / threadID-in-group
    const int nb0 = 64 * wc;

    float acc[2][8][4];
#pragma unroll
    for (int i = 0; i < 2; i++)
#pragma unroll
        for (int j = 0; j < 8; j++)
#pragma unroll
            for (int q = 0; q < 4; q++) acc[i][j][q] = 0.f;

#pragma unroll
    for (int k0 = 0; k0 < D; k0 += 8) {
        unsigned b[8][2];
        const float* wrow0 = ws + (k0 + qc) * SMP + nb0 + qr;
        const float* wrow1 = wrow0 + 4 * SMP;
#pragma unroll
        for (int j = 0; j < 8; j++) {
            b[j][0] = __float_as_uint(wrow0[8 * j]);
            b[j][1] = __float_as_uint(wrow1[8 * j]);
        }
#pragma unroll
        for (int i = 0; i < 2; i++) {
            const float* arow = xs + (32 * wr + 16 * i + qr) * SMP + k0 + qc;
            unsigned a0 = __float_as_uint(arow[0]);
            unsigned a1 = __float_as_uint(arow[8 * SMP]);
            unsigned a2 = __float_as_uint(arow[4]);
            unsigned a3 = __float_as_uint(arow[8 * SMP + 4]);
#pragma unroll
            for (int j = 0; j < 8; j++) {
                asm volatile(
                    "mma.sync.aligned.m16n8k8.row.col.f32.tf32.tf32.f32 "
                    "{%0,%1,%2,%3}, {%4,%5,%6,%7}, {%8,%9}, {%0,%1,%2,%3};\n"
                    : "+f"(acc[i][j][0]), "+f"(acc[i][j][1]),
                      "+f"(acc[i][j][2]), "+f"(acc[i][j][3])
                    : "r"(a0), "r"(a1), "r"(a2), "r"(a3),
                      "r"(b[j][0]), "r"(b[j][1]));
            }
        }
    }

    // ---- epilogue: write H ----
#pragma unroll
    for (int i = 0; i < 2; i++) {
        int r = row0 + 32 * wr + 16 * i + qr;
#pragma unroll
        for (int j = 0; j < 8; j++) {
            int c = nb0 + 8 * j + 2 * qc;
            if (r < nrows)
                *(float2*)(H + (size_t)r * D + c) =
                    make_float2(acc[i][j][0], acc[i][j][1]);
            if (r + 8 < nrows)
                *(float2*)(H + (size_t)(r + 8) * D + c) =
                    make_float2(acc[i][j][2], acc[i][j][3]);
        }
    }
}

// ============================================================
// CSR build
// ============================================================
__global__ void hist_deg_kernel(const int* __restrict__ src,
                                const int* __restrict__ dst,
                                const float* __restrict__ wt, int E)
{
    int e = blockIdx.x * blockDim.x + threadIdx.x;
    if (e >= E) return;
    atomicAdd(&g_cnt[dst[e]], 1);
    atomicAdd(&g_deg[src[e]], wt[e]);
}

__global__ __launch_bounds__(256) void scan1_kernel(int nrows)
{
    __shared__ int wsum[8];
    int b = blockIdx.x, t = threadIdx.x;
    int base = b * SCAN_CHUNK + t * 4;
    int s = 0;
#pragma unroll
    for (int k = 0; k < 4; k++) {
        int idx = base + k;
        if (idx < nrows) s += g_cnt[idx];
    }
#pragma unroll
    for (int o = 16; o > 0; o >>= 1) s += __shfl_down_sync(0xffffffffu, s, o);
    if ((t & 31) == 0) wsum[t >> 5] = s;
    __syncthreads();
    if (t == 0) {
        int tot = 0;
#pragma unroll
        for (int i = 0; i < 8; i++) tot += wsum[i];
        g_bsum[b] = tot;
    }
}

__global__ void scan2_kernel(int nblocks, int nrows)
{
    if (threadIdx.x == 0) {
        int run = 0;
        for (int i = 0; i < nblocks; i++) {
            g_boff[i] = run;
            run += g_bsum[i];
        }
        g_rs[nrows] = run;
    }
}

__global__ __launch_bounds__(256) void scan3_kernel(int nrows)
{
    __shared__ int woff[8];
    int b = blockIdx.x, t = threadIdx.x;
    int base = b * SCAN_CHUNK + t * 4;
    int c[4];
    int s = 0;
#pragma unroll
    for (int k = 0; k < 4; k++) {
        int idx = base + k;
        c[k] = (idx < nrows) ? g_cnt[idx] : 0;
        s += c[k];
    }
    int incl = s;
#pragma unroll
    for (int o = 1; o < 32; o <<= 1) {
        int y = __shfl_up_sync(0xffffffffu, incl, o);
        if ((t & 31) >= o) incl += y;
    }
    if ((t & 31) == 31) woff[t >> 5] = incl;
    __syncthreads();
    if (t < 8) {
        int v = woff[t];
        int iv = v;
#pragma unroll
        for (int o = 1; o < 8; o <<= 1) {
            int y = __shfl_up_sync(0x000000ffu, iv, o);
            if (t >= o) iv += y;
        }
        woff[t] = iv - v;
    }
    __syncthreads();
    int excl = incl - s + woff[t >> 5] + g_boff[b];
#pragma unroll
    for (int k = 0; k < 4; k++) {
        int idx = base + k;
        if (idx < nrows) g_rs[idx] = excl;
        excl += c[k];
    }
}

__global__ void fill_kernel(const int* __restrict__ src,
                            const int* __restrict__ dst,
                            const float* __restrict__ wt, int E)
{
    int e = blockIdx.x * blockDim.x + threadIdx.x;
    if (e >= E) return;
    int slot = atomicAdd(&g_pos[dst[e]], 1);
    g_edges[slot] = make_int2(src[e], __float_as_int(wt[e]));
}

// ============================================================
// Fused CSR gather + BN column statistics.
// Grid-stride, warp per node; per-block stats reduced once.
// ============================================================
__global__ __launch_bounds__(256) void gather_stats_kernel(
    const float* __restrict__ H, float* __restrict__ AGG, int nrows)
{
    __shared__ float4 ssum[8][32];
    __shared__ float4 ssq[8][32];
    const int warp = threadIdx.x >> 5;
    const int lane = threadIdx.x & 31;
    float4 cs = make_float4(0.f, 0.f, 0.f, 0.f);
    float4 cq = make_float4(0.f, 0.f, 0.f, 0.f);

    for (int n = blockIdx.x * 8 + warp; n < nrows; n += gridDim.x * 8) {
        int beg = g_rs[n], end = g_rs[n + 1];
        float4 acc = make_float4(0.f, 0.f, 0.f, 0.f);
        for (int base = beg; base < end; base += 32) {
            int m = min(32, end - base);
            int2 ed = make_int2(0, 0);
            if (lane < m) ed = g_edges[base + lane];
            for (int j = 0; j < m; j++) {
                int s = __shfl_sync(0xffffffffu, ed.x, j);
                float w = __int_as_float(__shfl_sync(0xffffffffu, ed.y, j));
                float4 v = ((const float4*)H)[(size_t)s * 32 + lane];
                acc.x = fmaf(w, v.x, acc.x);
                acc.y = fmaf(w, v.y, acc.y);
                acc.z = fmaf(w, v.z, acc.z);
                acc.w = fmaf(w, v.w, acc.w);
            }
        }
        ((float4*)AGG)[(size_t)n * 32 + lane] = acc;
        cs.x += acc.x; cs.y += acc.y; cs.z += acc.z; cs.w += acc.w;
        cq.x = fmaf(acc.x, acc.x, cq.x);
        cq.y = fmaf(acc.y, acc.y, cq.y);
        cq.z = fmaf(acc.z, acc.z, cq.z);
        cq.w = fmaf(acc.w, acc.w, cq.w);
    }
    ssum[warp][lane] = cs;
    ssq[warp][lane] = cq;
    __syncthreads();
    if (warp == 0) {
#pragma unroll
        for (int i = 1; i < 8; i++) {
            float4 a = ssum[i][lane], b = ssq[i][lane];
            cs.x += a.x; cs.y += a.y; cs.z += a.z; cs.w += a.w;
            cq.x += b.x; cq.y += b.y; cq.z += b.z; cq.w += b.w;
        }
        float* ps = &g_colsum[4 * lane];
        float* pq = &g_colsumsq[4 * lane];
        asm volatile("red.global.add.v4.f32 [%0], {%1,%2,%3,%4};"
                     :: "l"(ps), "f"(cs.x), "f"(cs.y), "f"(cs.z), "f"(cs.w) : "memory");
        asm volatile("red.global.add.v4.f32 [%0], {%1,%2,%3,%4};"
                     :: "l"(pq), "f"(cq.x), "f"(cq.y), "f"(cq.z), "f"(cq.w) : "memory");
    }
}

__global__ void bnfinalize_kernel(const float* __restrict__ gamma,
                                  const float* __restrict__ beta, float inv_n)
{
    int c = threadIdx.x;
    float m = g_colsum[c] * inv_n;
    float var = fmaf(-m, m, g_colsumsq[c] * inv_n);
    float inv = rsqrtf(var + BN_EPS);
    float sc = gamma[c] * inv;
    g_scale[c] = sc;
    g_shift[c] = fmaf(-sc, m, beta[c]);
}

// v[c] = sum_n deg[n] * relu(scale_c * agg[n,c] + shift_c)
__global__ __launch_bounds__(256) void vreduce_kernel(
    const float* __restrict__ AGG, int nrows)
{
    __shared__ float4 ssum[8][32];
    const int kr = threadIdx.x & 31;
    const int rr = threadIdx.x >> 5;
    float4 sc4 = ((const float4*)g_scale)[kr];
    float4 sh4 = ((const float4*)g_shift)[kr];
    float4 acc = make_float4(0.f, 0.f, 0.f, 0.f);
    for (int n = blockIdx.x * 8 + rr; n < nrows; n += gridDim.x * 8) {
        float dn = g_deg[n];
        float4 a = ((const float4*)AGG)[(size_t)n * 32 + kr];
        float x0 = fmaxf(fmaf(sc4.x, a.x, sh4.x), 0.f);
        float x1 = fmaxf(fmaf(sc4.y, a.y, sh4.y), 0.f);
        float x2 = fmaxf(fmaf(sc4.z, a.z, sh4.z), 0.f);
        float x3 = fmaxf(fmaf(sc4.w, a.w, sh4.w), 0.f);
        acc.x = fmaf(dn, x0, acc.x);
        acc.y = fmaf(dn, x1, acc.y);
        acc.z = fmaf(dn, x2, acc.z);
        acc.w = fmaf(dn, x3, acc.w);
    }
    ssum[rr][kr] = acc;
    __syncthreads();
    if (rr == 0) {
#pragma unroll
        for (int i = 1; i < 8; i++) {
            float4 a = ssum[i][kr];
            acc.x += a.x; acc.y += a.y; acc.z += a.z; acc.w += a.w;
        }
        float* pv = &g_v[4 * kr];
        asm volatile("red.global.add.v4.f32 [%0], {%1,%2,%3,%4};"
                     :: "l"(pv), "f"(acc.x), "f"(acc.y), "f"(acc.z), "f"(acc.w) : "memory");
    }
}

__global__ void final_kernel(const float* __restrict__ W2,
                             const float* __restrict__ b2,
                             float* __restrict__ out, float nf)
{
    int c = threadIdx.x;
    float s = 0.f;
#pragma unroll 8
    for (int k = 0; k < D; k++) s = fmaf(g_v[k], W2[k * DOUT + c], s);
    out[c] = fmaf(nf, b2[c], s);
}

// ============================================================

extern "C" void kernel_launch(void* const* d_in, const int* in_sizes, int n_in,
                              void* d_out, int out_size)
{
    const float* nf     = (const float*)d_in[0];
    const int*   ei     = (const int*)d_in[1];
    const float* ew     = (const float*)d_in[2];
    const float* W0     = (const float*)d_in[3];
    const float* W1     = (const float*)d_in[5];
    const float* W2     = (const float*)d_in[7];
    const float* b2     = (const float*)d_in[8];
    const float* gamma0 = (const float*)d_in[9];
    const float* beta0  = (const float*)d_in[10];
    const float* gamma1 = (const float*)d_in[11];
    const float* beta1  = (const float*)d_in[12];

    const int E = in_sizes[2];
    const int N = in_sizes[0] / D;
    const int* src = ei;
    const int* dst = ei + E;

    float *p_h, *p_agg, *p_cs, *p_cq, *p_deg, *p_v;
    int *p_cnt, *p_rs, *p_pos;
    cudaGetSymbolAddress((void**)&p_h, g_h);
    cudaGetSymbolAddress((void**)&p_agg, g_agg);
    cudaGetSymbolAddress((void**)&p_cs, g_colsum);
    cudaGetSymbolAddress((void**)&p_cq, g_colsumsq);
    cudaGetSymbolAddress((void**)&p_deg, g_deg);
    cudaGetSymbolAddress((void**)&p_v, g_v);
    cudaGetSymbolAddress((void**)&p_cnt, g_cnt);
    cudaGetSymbolAddress((void**)&p_rs, g_rs);
    cudaGetSymbolAddress((void**)&p_pos, g_pos);

    const size_t smem = (size_t)(2 * 128 * SMP) * sizeof(float);  // 135168 B
    cudaFuncSetAttribute((const void*)gemm_tc_kernel<false>,
                         cudaFuncAttributeMaxDynamicSharedMemorySize, (int)smem);
    cudaFuncSetAttribute((const void*)gemm_tc_kernel<true>,
                         cudaFuncAttributeMaxDynamicSharedMemorySize, (int)smem);

    const int gemm_blocks = (N + 127) / 128;
    const int stat_blocks = 1184;
    const int scan_blocks = (N + SCAN_CHUNK - 1) / SCAN_CHUNK;
    const int edge_blocks = (E + 255) / 256;

    // ---- init ----
    cudaMemsetAsync(p_cnt, 0, (size_t)N * sizeof(int), 0);
    cudaMemsetAsync(p_deg, 0, (size_t)N * sizeof(float), 0);
    cudaMemsetAsync(p_cs, 0, D * sizeof(float), 0);
    cudaMemsetAsync(p_cq, 0, D * sizeof(float), 0);
    cudaMemsetAsync(p_v, 0, D * sizeof(float), 0);

    // ---- CSR build (by dst) + weighted out-degree ----
    hist_deg_kernel<<<edge_blocks, 256>>>(src, dst, ew, E);
    scan1_kernel<<<scan_blocks, 256>>>(N);
    scan2_kernel<<<1, 32>>>(scan_blocks, N);
    scan3_kernel<<<scan_blocks, 256>>>(N);
    cudaMemcpyAsync(p_pos, p_rs, (size_t)N * sizeof(int),
                    cudaMemcpyDeviceToDevice, 0);
    fill_kernel<<<edge_blocks, 256>>>(src, dst, ew, E);

    // ---- layer 0 ----
    gemm_tc_kernel<false><<<gemm_blocks, 256, smem>>>(nf, W0, p_h, N);
    gather_stats_kernel<<<stat_blocks, 256>>>(p_h, p_agg, N);
    bnfinalize_kernel<<<1, D>>>(gamma0, beta0, 1.0f / (float)N);

    // ---- layer 1 ----
    gemm_tc_kernel<true><<<gemm_blocks, 256, smem>>>(p_agg, W1, p_h, N);
    cudaMemsetAsync(p_cs, 0, D * sizeof(float), 0);
    cudaMemsetAsync(p_cq, 0, D * sizeof(float), 0);
    gather_stats_kernel<<<stat_blocks, 256>>>(p_h, p_agg, N);
    bnfinalize_kernel<<<1, D>>>(gamma1, beta1, 1.0f / (float)N);

    // ---- layer 2 collapsed algebraically ----
    vreduce_kernel<<<stat_blocks, 256>>>(p_agg, N);
    final_kernel<<<1, DOUT>>>(W2, b2, (float*)d_out, (float)N);
}

// round 13
// speedup vs baseline: 2.0744x; 1.0816x over previous
#include <cuda_runtime.h>
#include <cuda_fp16.h>

#define NODES_MAX 100000
#define EDGES_MAX 1600000
#define D 128
#define DOUT 64
#define BN_EPS 1e-5f
#define SCAN_CHUNK 1024
#define SCAN_NB ((NODES_MAX + SCAN_CHUNK - 1) / SCAN_CHUNK)
#define SMP 132   // padded smem row stride (words)

// ---- scratch (static device globals; no allocation) ----
__device__ __align__(16) __half g_h[(size_t)NODES_MAX * D];  // 25.6 MB fp16 H
__device__ __align__(16) float g_agg[(size_t)NODES_MAX * D]; // 51.2 MB gather target
__device__ float g_colsum[D];
__device__ float g_colsumsq[D];
__device__ float g_scale[D];
__device__ float g_shift[D];
__device__ float g_deg[NODES_MAX];               // weighted out-degree
__device__ float g_v[D];                         // sum_n d_n * x1[n]
__device__ int   g_ctr[2];                       // last-block counters
// CSR-by-dst
__device__ int  g_cnt[NODES_MAX];
__device__ int  g_rs[NODES_MAX + 1];
__device__ int  g_pos[NODES_MAX];
__device__ int  g_bsum[SCAN_NB + 1];
__device__ int  g_boff[SCAN_NB + 1];
__device__ __align__(16) int2 g_edges[EDGES_MAX]; // {src, bitcast(w)} sorted by dst

__device__ __forceinline__ float to_tf32(float x) {
    unsigned u;
    asm("cvt.rna.tf32.f32 %0, %1;" : "=r"(u) : "f"(x));
    return __int_as_float(u);
}

// ============================================================
// TF32 tensor-core GEMM: H[n,m] = sum_k f(X[n,k]) * W[k,m], H in fp16.
// FUSE: f(x) = relu(scale_k * x + shift_k)  (BN+ReLU of previous layer)
// Block: 256 threads, 128x128 output tile; warp tile 32x64.
// ============================================================
template <bool FUSE>
__global__ __launch_bounds__(256) void gemm_tc_kernel(
    const float* __restrict__ X, const float* __restrict__ W,
    __half* __restrict__ H, int nrows)
{
    extern __shared__ float sm[];
    float* xs = sm;             // [128][SMP]
    float* ws = sm + 128 * SMP; // [128][SMP]
    const int tid = threadIdx.x;
    const int row0 = blockIdx.x * 128;

    // ---- load W (128x128) -> smem (tf32-rounded, padded) ----
#pragma unroll
    for (int it = 0; it < 16; it++) {
        int i = tid + 256 * it;           // float4 index
        int r = i >> 5, c4 = i & 31;
        float4 v = ((const float4*)W)[r * 32 + c4];
        v.x = to_tf32(v.x); v.y = to_tf32(v.y);
        v.z = to_tf32(v.z); v.w = to_tf32(v.w);
        *(float4*)(ws + r * SMP + c4 * 4) = v;
    }

    // ---- load X tile (128x128) -> smem (BN+ReLU fused, tf32, padded) ----
#pragma unroll
    for (int it = 0; it < 16; it++) {
        int i = tid + 256 * it;
        int r = i >> 5, c4 = i & 31;
        float4 v = make_float4(0.f, 0.f, 0.f, 0.f);
        int grow = row0 + r;
        if (grow < nrows) v = ((const float4*)X)[(size_t)grow * 32 + c4];
        if (FUSE) {
            float4 sc4 = ((const float4*)g_scale)[c4];
            float4 sh4 = ((const float4*)g_shift)[c4];
            v.x = fmaxf(fmaf(sc4.x, v.x, sh4.x), 0.f);
            v.y = fmaxf(fmaf(sc4.y, v.y, sh4.y), 0.f);
            v.z = fmaxf(fmaf(sc4.z, v.z, sh4.z), 0.f);
            v.w = fmaxf(fmaf(sc4.w, v.w, sh4.w), 0.f);
        }
        v.x = to_tf32(v.x); v.y = to_tf32(v.y);
        v.z = to_tf32(v.z); v.w = to_tf32(v.w);
        *(float4*)(xs + r * SMP + c4 * 4) = v;
    }
    __syncthreads();

    const int warp = tid >> 5, lane = tid & 31;
    const int wr = warp >> 1, wc = warp & 1;   // warp tile: rows 32*wr, cols 64*wc
    const int qr = lane >> 2, qc = lane & 3;   // groupID / threadID-in-group
    const int nb0 = 64 * wc;

    float acc[2][8][4];
#pragma unroll
    for (int i = 0; i < 2; i++)
#pragma unroll
        for (int j = 0; j < 8; j++)
#pragma unroll
            for (int q = 0; q < 4; q++) acc[i][j][q] = 0.f;

#pragma unroll
    for (int k0 = 0; k0 < D; k0 += 8) {
        unsigned b[8][2];
        const float* wrow0 = ws + (k0 + qc) * SMP + nb0 + qr;
        const float* wrow1 = wrow0 + 4 * SMP;
#pragma unroll
        for (int j = 0; j < 8; j++) {
            b[j][0] = __float_as_uint(wrow0[8 * j]);
            b[j][1] = __float_as_uint(wrow1[8 * j]);
        }
#pragma unroll
        for (int i = 0; i < 2; i++) {
            const float* arow = xs + (32 * wr + 16 * i + qr) * SMP + k0 + qc;
            unsigned a0 = __float_as_uint(arow[0]);
            unsigned a1 = __float_as_uint(arow[8 * SMP]);
            unsigned a2 = __float_as_uint(arow[4]);
            unsigned a3 = __float_as_uint(arow[8 * SMP + 4]);
#pragma unroll
            for (int j = 0; j < 8; j++) {
                asm volatile(
                    "mma.sync.aligned.m16n8k8.row.col.f32.tf32.tf32.f32 "
                    "{%0,%1,%2,%3}, {%4,%5,%6,%7}, {%8,%9}, {%0,%1,%2,%3};\n"
                    : "+f"(acc[i][j][0]), "+f"(acc[i][j][1]),
                      "+f"(acc[i][j][2]), "+f"(acc[i][j][3])
                    : "r"(a0), "r"(a1), "r"(a2), "r"(a3),
                      "r"(b[j][0]), "r"(b[j][1]));
            }
        }
    }

    // ---- epilogue: write H in fp16 ----
#pragma unroll
    for (int i = 0; i < 2; i++) {
        int r = row0 + 32 * wr + 16 * i + qr;
#pragma unroll
        for (int j = 0; j < 8; j++) {
            int c = nb0 + 8 * j + 2 * qc;
            if (r < nrows)
                *(__half2*)(H + (size_t)r * D + c) =
                    __floats2half2_rn(acc[i][j][0], acc[i][j][1]);
            if (r + 8 < nrows)
                *(__half2*)(H + (size_t)(r + 8) * D + c) =
                    __floats2half2_rn(acc[i][j][2], acc[i][j][3]);
        }
    }
}

// ============================================================
// CSR build
// ============================================================
__global__ void hist_deg_kernel(const int* __restrict__ src,
                                const int* __restrict__ dst,
                                const float* __restrict__ wt, int E)
{
    int e = blockIdx.x * blockDim.x + threadIdx.x;
    if (e >= E) return;
    atomicAdd(&g_cnt[dst[e]], 1);
    atomicAdd(&g_deg[src[e]], wt[e]);
}

__global__ __launch_bounds__(256) void scan1_kernel(int nrows)
{
    __shared__ int wsum[8];
    int b = blockIdx.x, t = threadIdx.x;
    int base = b * SCAN_CHUNK + t * 4;
    int s = 0;
#pragma unroll
    for (int k = 0; k < 4; k++) {
        int idx = base + k;
        if (idx < nrows) s += g_cnt[idx];
    }
#pragma unroll
    for (int o = 16; o > 0; o >>= 1) s += __shfl_down_sync(0xffffffffu, s, o);
    if ((t & 31) == 0) wsum[t >> 5] = s;
    __syncthreads();
    if (t == 0) {
        int tot = 0;
#pragma unroll
        for (int i = 0; i < 8; i++) tot += wsum[i];
        g_bsum[b] = tot;
    }
}

__global__ void scan2_kernel(int nblocks, int nrows)
{
    if (threadIdx.x == 0) {
        int run = 0;
        for (int i = 0; i < nblocks; i++) {
            g_boff[i] = run;
            run += g_bsum[i];
        }
        g_rs[nrows] = run;
    }
}

__global__ __launch_bounds__(256) void scan3_kernel(int nrows)
{
    __shared__ int woff[8];
    int b = blockIdx.x, t = threadIdx.x;
    int base = b * SCAN_CHUNK + t * 4;
    int c[4];
    int s = 0;
#pragma unroll
    for (int k = 0; k < 4; k++) {
        int idx = base + k;
        c[k] = (idx < nrows) ? g_cnt[idx] : 0;
        s += c[k];
    }
    int incl = s;
#pragma unroll
    for (int o = 1; o < 32; o <<= 1) {
        int y = __shfl_up_sync(0xffffffffu, incl, o);
        if ((t & 31) >= o) incl += y;
    }
    if ((t & 31) == 31) woff[t >> 5] = incl;
    __syncthreads();
    if (t < 8) {
        int v = woff[t];
        int iv = v;
#pragma unroll
        for (int o = 1; o < 8; o <<= 1) {
            int y = __shfl_up_sync(0x000000ffu, iv, o);
            if (t >= o) iv += y;
        }
        woff[t] = iv - v;
    }
    __syncthreads();
    int excl = incl - s + woff[t >> 5] + g_boff[b];
#pragma unroll
    for (int k = 0; k < 4; k++) {
        int idx = base + k;
        if (idx < nrows) g_rs[idx] = excl;
        excl += c[k];
    }
}

__global__ void fill_kernel(const int* __restrict__ src,
                            const int* __restrict__ dst,
                            const float* __restrict__ wt, int E)
{
    int e = blockIdx.x * blockDim.x + threadIdx.x;
    if (e >= E) return;
    int slot = atomicAdd(&g_pos[dst[e]], 1);
    g_edges[slot] = make_int2(src[e], __float_as_int(wt[e]));
}

// ============================================================
// Fused CSR gather (fp16 H) + BN column statistics + last-block
// BN finalize (scale/shift) -- no separate bnfinalize kernel.
// ============================================================
__global__ __launch_bounds__(256) void gather_stats_kernel(
    const __half* __restrict__ H, float* __restrict__ AGG, int nrows,
    const float* __restrict__ gamma, const float* __restrict__ beta,
    float inv_n, int ctr_idx)
{
    __shared__ float4 ssum[8][32];
    __shared__ float4 ssq[8][32];
    __shared__ int s_last;
    const int warp = threadIdx.x >> 5;
    const int lane = threadIdx.x & 31;
    float4 cs = make_float4(0.f, 0.f, 0.f, 0.f);
    float4 cq = make_float4(0.f, 0.f, 0.f, 0.f);

    for (int n = blockIdx.x * 8 + warp; n < nrows; n += gridDim.x * 8) {
        int beg = g_rs[n], end = g_rs[n + 1];
        float4 acc = make_float4(0.f, 0.f, 0.f, 0.f);
        for (int base = beg; base < end; base += 32) {
            int m = min(32, end - base);
            int2 ed = make_int2(0, 0);
            if (lane < m) ed = g_edges[base + lane];
            for (int j = 0; j < m; j++) {
                int s = __shfl_sync(0xffffffffu, ed.x, j);
                float w = __int_as_float(__shfl_sync(0xffffffffu, ed.y, j));
                // 4 fp16 channels per lane (8 bytes)
                uint2 raw = *(const uint2*)(H + (size_t)s * D + 4 * lane);
                float2 v01 = __half22float2(*(__half2*)&raw.x);
                float2 v23 = __half22float2(*(__half2*)&raw.y);
                acc.x = fmaf(w, v01.x, acc.x);
                acc.y = fmaf(w, v01.y, acc.y);
                acc.z = fmaf(w, v23.x, acc.z);
                acc.w = fmaf(w, v23.y, acc.w);
            }
        }
        ((float4*)AGG)[(size_t)n * 32 + lane] = acc;
        cs.x += acc.x; cs.y += acc.y; cs.z += acc.z; cs.w += acc.w;
        cq.x = fmaf(acc.x, acc.x, cq.x);
        cq.y = fmaf(acc.y, acc.y, cq.y);
        cq.z = fmaf(acc.z, acc.z, cq.z);
        cq.w = fmaf(acc.w, acc.w, cq.w);
    }
    ssum[warp][lane] = cs;
    ssq[warp][lane] = cq;
    __syncthreads();
    if (warp == 0) {
#pragma unroll
        for (int i = 1; i < 8; i++) {
            float4 a = ssum[i][lane], b = ssq[i][lane];
            cs.x += a.x; cs.y += a.y; cs.z += a.z; cs.w += a.w;
            cq.x += b.x; cq.y += b.y; cq.z += b.z; cq.w += b.w;
        }
        float* ps = &g_colsum[4 * lane];
        float* pq = &g_colsumsq[4 * lane];
        asm volatile("red.global.add.v4.f32 [%0], {%1,%2,%3,%4};"
                     :: "l"(ps), "f"(cs.x), "f"(cs.y), "f"(cs.z), "f"(cs.w) : "memory");
        asm volatile("red.global.add.v4.f32 [%0], {%1,%2,%3,%4};"
                     :: "l"(pq), "f"(cq.x), "f"(cq.y), "f"(cq.z), "f"(cq.w) : "memory");
    }
    // last block computes BN scale/shift
    if (threadIdx.x == 0) {
        __threadfence();
        s_last = (atomicAdd(&g_ctr[ctr_idx], 1) == (int)gridDim.x - 1) ? 1 : 0;
    }
    __syncthreads();
    if (s_last && threadIdx.x < D) {
        int c = threadIdx.x;
        float m = g_colsum[c] * inv_n;
        float var = fmaf(-m, m, g_colsumsq[c] * inv_n);
        float inv = rsqrtf(var + BN_EPS);
        float sc = gamma[c] * inv;
        g_scale[c] = sc;
        g_shift[c] = fmaf(-sc, m, beta[c]);
    }
}

// v[c] = sum_n deg[n] * relu(scale_c * agg[n,c] + shift_c)
__global__ __launch_bounds__(256) void vreduce_kernel(
    const float* __restrict__ AGG, int nrows)
{
    __shared__ float4 ssum[8][32];
    const int kr = threadIdx.x & 31;
    const int rr = threadIdx.x >> 5;
    float4 sc4 = ((const float4*)g_scale)[kr];
    float4 sh4 = ((const float4*)g_shift)[kr];
    float4 acc = make_float4(0.f, 0.f, 0.f, 0.f);
    for (int n = blockIdx.x * 8 + rr; n < nrows; n += gridDim.x * 8) {
        float dn = g_deg[n];
        float4 a = ((const float4*)AGG)[(size_t)n * 32 + kr];
        float x0 = fmaxf(fmaf(sc4.x, a.x, sh4.x), 0.f);
        float x1 = fmaxf(fmaf(sc4.y, a.y, sh4.y), 0.f);
        float x2 = fmaxf(fmaf(sc4.z, a.z, sh4.z), 0.f);
        float x3 = fmaxf(fmaf(sc4.w, a.w, sh4.w), 0.f);
        acc.x = fmaf(dn, x0, acc.x);
        acc.y = fmaf(dn, x1, acc.y);
        acc.z = fmaf(dn, x2, acc.z);
        acc.w = fmaf(dn, x3, acc.w);
    }
    ssum[rr][kr] = acc;
    __syncthreads();
    if (rr == 0) {
#pragma unroll
        for (int i = 1; i < 8; i++) {
            float4 a = ssum[i][kr];
            acc.x += a.x; acc.y += a.y; acc.z += a.z; acc.w += a.w;
        }
        float* pv = &g_v[4 * kr];
        asm volatile("red.global.add.v4.f32 [%0], {%1,%2,%3,%4};"
                     :: "l"(pv), "f"(acc.x), "f"(acc.y), "f"(acc.z), "f"(acc.w) : "memory");
    }
}

__global__ void final_kernel(const float* __restrict__ W2,
                             const float* __restrict__ b2,
                             float* __restrict__ out, float nf)
{
    int c = threadIdx.x;
    float s = 0.f;
#pragma unroll 8
    for (int k = 0; k < D; k++) s = fmaf(g_v[k], W2[k * DOUT + c], s);
    out[c] = fmaf(nf, b2[c], s);
}

// ============================================================

extern "C" void kernel_launch(void* const* d_in, const int* in_sizes, int n_in,
                              void* d_out, int out_size)
{
    const float* nf     = (const float*)d_in[0];
    const int*   ei     = (const int*)d_in[1];
    const float* ew     = (const float*)d_in[2];
    const float* W0     = (const float*)d_in[3];
    const float* W1     = (const float*)d_in[5];
    const float* W2     = (const float*)d_in[7];
    const float* b2     = (const float*)d_in[8];
    const float* gamma0 = (const float*)d_in[9];
    const float* beta0  = (const float*)d_in[10];
    const float* gamma1 = (const float*)d_in[11];
    const float* beta1  = (const float*)d_in[12];

    const int E = in_sizes[2];
    const int N = in_sizes[0] / D;
    const int* src = ei;
    const int* dst = ei + E;

    __half* p_h;
    float *p_agg, *p_cs, *p_cq, *p_deg, *p_v;
    int *p_cnt, *p_rs, *p_pos, *p_ctr;
    cudaGetSymbolAddress((void**)&p_h, g_h);
    cudaGetSymbolAddress((void**)&p_agg, g_agg);
    cudaGetSymbolAddress((void**)&p_cs, g_colsum);
    cudaGetSymbolAddress((void**)&p_cq, g_colsumsq);
    cudaGetSymbolAddress((void**)&p_deg, g_deg);
    cudaGetSymbolAddress((void**)&p_v, g_v);
    cudaGetSymbolAddress((void**)&p_cnt, g_cnt);
    cudaGetSymbolAddress((void**)&p_rs, g_rs);
    cudaGetSymbolAddress((void**)&p_pos, g_pos);
    cudaGetSymbolAddress((void**)&p_ctr, g_ctr);

    const size_t smem = (size_t)(2 * 128 * SMP) * sizeof(float);  // 135168 B
    cudaFuncSetAttribute((const void*)gemm_tc_kernel<false>,
                         cudaFuncAttributeMaxDynamicSharedMemorySize, (int)smem);
    cudaFuncSetAttribute((const void*)gemm_tc_kernel<true>,
                         cudaFuncAttributeMaxDynamicSharedMemorySize, (int)smem);

    const int gemm_blocks = (N + 127) / 128;
    const int stat_blocks = 1184;
    const int scan_blocks = (N + SCAN_CHUNK - 1) / SCAN_CHUNK;
    const int edge_blocks = (E + 255) / 256;
    const float inv_n = 1.0f / (float)N;

    // ---- init ----
    cudaMemsetAsync(p_cnt, 0, (size_t)N * sizeof(int), 0);
    cudaMemsetAsync(p_deg, 0, (size_t)N * sizeof(float), 0);
    cudaMemsetAsync(p_cs, 0, D * sizeof(float), 0);
    cudaMemsetAsync(p_cq, 0, D * sizeof(float), 0);
    cudaMemsetAsync(p_v, 0, D * sizeof(float), 0);
    cudaMemsetAsync(p_ctr, 0, 2 * sizeof(int), 0);

    // ---- CSR build (by dst) + weighted out-degree ----
    hist_deg_kernel<<<edge_blocks, 256>>>(src, dst, ew, E);
    scan1_kernel<<<scan_blocks, 256>>>(N);
    scan2_kernel<<<1, 32>>>(scan_blocks, N);
    scan3_kernel<<<scan_blocks, 256>>>(N);
    cudaMemcpyAsync(p_pos, p_rs, (size_t)N * sizeof(int),
                    cudaMemcpyDeviceToDevice, 0);
    fill_kernel<<<edge_blocks, 256>>>(src, dst, ew, E);

    // ---- layer 0 ----
    gemm_tc_kernel<false><<<gemm_blocks, 256, smem>>>(nf, W0, p_h, N);
    gather_stats_kernel<<<stat_blocks, 256>>>(p_h, p_agg, N,
                                              gamma0, beta0, inv_n, 0);

    // ---- layer 1 ----
    gemm_tc_kernel<true><<<gemm_blocks, 256, smem>>>(p_agg, W1, p_h, N);
    cudaMemsetAsync(p_cs, 0, D * sizeof(float), 0);
    cudaMemsetAsync(p_cq, 0, D * sizeof(float), 0);
    gather_stats_kernel<<<stat_blocks, 256>>>(p_h, p_agg, N,
                                              gamma1, beta1, inv_n, 1);

    // ---- layer 2 collapsed algebraically ----
    vreduce_kernel<<<stat_blocks, 256>>>(p_agg, N);
    final_kernel<<<1, DOUT>>>(W2, b2, (float*)d_out, (float)N);
}

// round 17
// speedup vs baseline: 2.1930x; 1.0572x over previous
#include <cuda_runtime.h>
#include <cuda_fp16.h>

#define NODES_MAX 100000
#define EDGES_MAX 1600000
#define D 128
#define DOUT 64
#define BN_EPS 1e-5f
#define SCAN_CHUNK 1024
#define SCAN_NB ((NODES_MAX + SCAN_CHUNK - 1) / SCAN_CHUNK)
#define SMP 132   // padded smem row stride (words)

// ---- scratch (static device globals; no allocation) ----
__device__ __align__(16) __half g_h[(size_t)NODES_MAX * D];  // 25.6 MB fp16 H
__device__ __align__(16) float g_agg[(size_t)NODES_MAX * D]; // 51.2 MB gather target
__device__ float g_cs[2][D];                     // per-layer column sums
__device__ float g_cq[2][D];                     // per-layer column sumsq
__device__ float g_scale[D];
__device__ float g_shift[D];
__device__ float g_deg[NODES_MAX];               // weighted out-degree
__device__ float g_v[D];                         // sum_n d_n * x1[n]
__device__ int   g_ctr[3];                       // last-block counters
// CSR-by-dst
__device__ int  g_cnt[NODES_MAX];
__device__ int  g_rs[NODES_MAX + 1];
__device__ int  g_pos[NODES_MAX];
__device__ int  g_bsum[SCAN_NB + 1];
__device__ int  g_boff[SCAN_NB + 1];
__device__ __align__(16) int2 g_edges[EDGES_MAX]; // {src, bitcast(w)} sorted by dst

__device__ __forceinline__ float to_tf32(float x) {
    unsigned u;
    asm("cvt.rna.tf32.f32 %0, %1;" : "=r"(u) : "f"(x));
    return __int_as_float(u);
}

// ============================================================
// One-shot zero init (replaces 8 memset graph nodes)
// ============================================================
__global__ __launch_bounds__(256) void init_kernel(int nrows)
{
    int i = blockIdx.x * 256 + threadIdx.x;
    if (i < nrows) {
        g_cnt[i] = 0;
        g_deg[i] = 0.f;
    }
    if (i < D) {
        g_cs[0][i] = 0.f; g_cs[1][i] = 0.f;
        g_cq[0][i] = 0.f; g_cq[1][i] = 0.f;
        g_v[i] = 0.f;
    }
    if (i < 3) g_ctr[i] = 0;
}

// ============================================================
// TF32 tensor-core GEMM: H[n,m] = sum_k f(X[n,k]) * W[k,m], H in fp16.
// FUSE: f(x) = relu(scale_k * x + shift_k)  (BN+ReLU of previous layer)
// Block: 256 threads, 128x128 output tile; warp tile 32x64.
// ============================================================
template <bool FUSE>
__global__ __launch_bounds__(256) void gemm_tc_kernel(
    const float* __restrict__ X, const float* __restrict__ W,
    __half* __restrict__ H, int nrows)
{
    extern __shared__ float sm[];
    float* xs = sm;             // [128][SMP]
    float* ws = sm + 128 * SMP; // [128][SMP]
    const int tid = threadIdx.x;
    const int row0 = blockIdx.x * 128;

    // ---- load W (128x128) -> smem (tf32-rounded, padded) ----
#pragma unroll
    for (int it = 0; it < 16; it++) {
        int i = tid + 256 * it;           // float4 index
        int r = i >> 5, c4 = i & 31;
        float4 v = ((const float4*)W)[r * 32 + c4];
        v.x = to_tf32(v.x); v.y = to_tf32(v.y);
        v.z = to_tf32(v.z); v.w = to_tf32(v.w);
        *(float4*)(ws + r * SMP + c4 * 4) = v;
    }

    // ---- load X tile (128x128) -> smem (BN+ReLU fused, tf32, padded) ----
#pragma unroll
    for (int it = 0; it < 16; it++) {
        int i = tid + 256 * it;
        int r = i >> 5, c4 = i & 31;
        float4 v = make_float4(0.f, 0.f, 0.f, 0.f);
        int grow = row0 + r;
        if (grow < nrows) v = ((const float4*)X)[(size_t)grow * 32 + c4];
        if (FUSE) {
            float4 sc4 = ((const float4*)g_scale)[c4];
            float4 sh4 = ((const float4*)g_shift)[c4];
            v.x = fmaxf(fmaf(sc4.x, v.x, sh4.x), 0.f);
            v.y = fmaxf(fmaf(sc4.y, v.y, sh4.y), 0.f);
            v.z = fmaxf(fmaf(sc4.z, v.z, sh4.z), 0.f);
            v.w = fmaxf(fmaf(sc4.w, v.w, sh4.w), 0.f);
        }
        v.x = to_tf32(v.x); v.y = to_tf32(v.y);
        v.z = to_tf32(v.z); v.w = to_tf32(v.w);
        *(float4*)(xs + r * SMP + c4 * 4) = v;
    }
    __syncthreads();

    const int warp = tid >> 5, lane = tid & 31;
    const int wr = warp >> 1, wc = warp & 1;   // warp tile: rows 32*wr, cols 64*wc
    const int qr = lane >> 2, qc = lane & 3;   // groupID / threadID-in-group
    const int nb0 = 64 * wc;

    float acc[2][8][4];
#pragma unroll
    for (int i = 0; i < 2; i++)
#pragma unroll
        for (int j = 0; j < 8; j++)
#pragma unroll
            for (int q = 0; q < 4; q++) acc[i][j][q] = 0.f;

#pragma unroll
    for (int k0 = 0; k0 < D; k0 += 8) {
        unsigned b[8][2];
        const float* wrow0 = ws + (k0 + qc) * SMP + nb0 + qr;
        const float* wrow1 = wrow0 + 4 * SMP;
#pragma unroll
        for (int j = 0; j < 8; j++) {
            b[j][0] = __float_as_uint(wrow0[8 * j]);
            b[j][1] = __float_as_uint(wrow1[8 * j]);
        }
#pragma unroll
        for (int i = 0; i < 2; i++) {
            const float* arow = xs + (32 * wr + 16 * i + qr) * SMP + k0 + qc;
            unsigned a0 = __float_as_uint(arow[0]);
            unsigned a1 = __float_as_uint(arow[8 * SMP]);
            unsigned a2 = __float_as_uint(arow[4]);
            unsigned a3 = __float_as_uint(arow[8 * SMP + 4]);
#pragma unroll
            for (int j = 0; j < 8; j++) {
                asm volatile(
                    "mma.sync.aligned.m16n8k8.row.col.f32.tf32.tf32.f32 "
                    "{%0,%1,%2,%3}, {%4,%5,%6,%7}, {%8,%9}, {%0,%1,%2,%3};\n"
                    : "+f"(acc[i][j][0]), "+f"(acc[i][j][1]),
                      "+f"(acc[i][j][2]), "+f"(acc[i][j][3])
                    : "r"(a0), "r"(a1), "r"(a2), "r"(a3),
                      "r"(b[j][0]), "r"(b[j][1]));
            }
        }
    }

    // ---- epilogue: write H in fp16 ----
#pragma unroll
    for (int i = 0; i < 2; i++) {
        int r = row0 + 32 * wr + 16 * i + qr;
#pragma unroll
        for (int j = 0; j < 8; j++) {
            int c = nb0 + 8 * j + 2 * qc;
            if (r < nrows)
                *(__half2*)(H + (size_t)r * D + c) =
                    __floats2half2_rn(acc[i][j][0], acc[i][j][1]);
            if (r + 8 < nrows)
                *(__half2*)(H + (size_t)(r + 8) * D + c) =
                    __floats2half2_rn(acc[i][j][2], acc[i][j][3]);
        }
    }
}

// ============================================================
// CSR build
// ============================================================
__global__ void hist_deg_kernel(const int* __restrict__ src,
                                const int* __restrict__ dst,
                                const float* __restrict__ wt, int E)
{
    int e = blockIdx.x * blockDim.x + threadIdx.x;
    if (e >= E) return;
    atomicAdd(&g_cnt[dst[e]], 1);
    atomicAdd(&g_deg[src[e]], wt[e]);
}

__global__ __launch_bounds__(256) void scan1_kernel(int nrows)
{
    __shared__ int wsum[8];
    int b = blockIdx.x, t = threadIdx.x;
    int base = b * SCAN_CHUNK + t * 4;
    int s = 0;
#pragma unroll
    for (int k = 0; k < 4; k++) {
        int idx = base + k;
        if (idx < nrows) s += g_cnt[idx];
    }
#pragma unroll
    for (int o = 16; o > 0; o >>= 1) s += __shfl_down_sync(0xffffffffu, s, o);
    if ((t & 31) == 0) wsum[t >> 5] = s;
    __syncthreads();
    if (t == 0) {
        int tot = 0;
#pragma unroll
        for (int i = 0; i < 8; i++) tot += wsum[i];
        g_bsum[b] = tot;
    }
}

// warp-parallel exclusive scan of chunk sums (nblocks <= 128)
__global__ void scan2_kernel(int nblocks, int nrows)
{
    __shared__ int wsum[4];
    __shared__ int woff[4];
    int t = threadIdx.x;       // 0..127
    int lane = t & 31;
    int v = (t < nblocks) ? g_bsum[t] : 0;
    int incl = v;
#pragma unroll
    for (int o = 1; o < 32; o <<= 1) {
        int y = __shfl_up_sync(0xffffffffu, incl, o);
        if (lane >= o) incl += y;
    }
    if (lane == 31) wsum[t >> 5] = incl;
    __syncthreads();
    if (t == 0) {
        int run = 0;
#pragma unroll
        for (int i = 0; i < 4; i++) { woff[i] = run; run += wsum[i]; }
    }
    __syncthreads();
    int excl = incl - v + woff[t >> 5];
    if (t < nblocks) g_boff[t] = excl;
    if (t == nblocks - 1) g_rs[nrows] = excl + v;
}

// per-chunk exclusive scan -> row_start (also seeds g_pos, replacing memcpy)
__global__ __launch_bounds__(256) void scan3_kernel(int nrows)
{
    __shared__ int woff[8];
    int b = blockIdx.x, t = threadIdx.x;
    int base = b * SCAN_CHUNK + t * 4;
    int c[4];
    int s = 0;
#pragma unroll
    for (int k = 0; k < 4; k++) {
        int idx = base + k;
        c[k] = (idx < nrows) ? g_cnt[idx] : 0;
        s += c[k];
    }
    int incl = s;
#pragma unroll
    for (int o = 1; o < 32; o <<= 1) {
        int y = __shfl_up_sync(0xffffffffu, incl, o);
        if ((t & 31) >= o) incl += y;
    }
    if ((t & 31) == 31) woff[t >> 5] = incl;
    __syncthreads();
    if (t < 8) {
        int v = woff[t];
        int iv = v;
#pragma unroll
        for (int o = 1; o < 8; o <<= 1) {
            int y = __shfl_up_sync(0x000000ffu, iv, o);
            if (t >= o) iv += y;
        }
        woff[t] = iv - v;
    }
    __syncthreads();
    int excl = incl - s + woff[t >> 5] + g_boff[b];
#pragma unroll
    for (int k = 0; k < 4; k++) {
        int idx = base + k;
        if (idx < nrows) { g_rs[idx] = excl; g_pos[idx] = excl; }
        excl += c[k];
    }
}

__global__ void fill_kernel(const int* __restrict__ src,
                            const int* __restrict__ dst,
                            const float* __restrict__ wt, int E)
{
    int e = blockIdx.x * blockDim.x + threadIdx.x;
    if (e >= E) return;
    int slot = atomicAdd(&g_pos[dst[e]], 1);
    g_edges[slot] = make_int2(src[e], __float_as_int(wt[e]));
}

// ============================================================
// Fused CSR gather (fp16 H) + BN column statistics + last-block
// BN finalize (scale/shift).  Inner edge loop unrolled x2 with
// dual accumulators for MLP / FFMA-chain ILP.
// ============================================================
__global__ __launch_bounds__(256) void gather_stats_kernel(
    const __half* __restrict__ H, float* __restrict__ AGG, int nrows,
    const float* __restrict__ gamma, const float* __restrict__ beta,
    float inv_n, int ctr_idx)
{
    __shared__ float4 ssum[8][32];
    __shared__ float4 ssq[8][32];
    __shared__ int s_last;
    const int warp = threadIdx.x >> 5;
    const int lane = threadIdx.x & 31;
    float* csbuf = g_cs[ctr_idx];
    float* cqbuf = g_cq[ctr_idx];
    float4 cs = make_float4(0.f, 0.f, 0.f, 0.f);
    float4 cq = make_float4(0.f, 0.f, 0.f, 0.f);

    for (int n = blockIdx.x * 8 + warp; n < nrows; n += gridDim.x * 8) {
        int beg = g_rs[n], end = g_rs[n + 1];
        float4 acc0 = make_float4(0.f, 0.f, 0.f, 0.f);
        float4 acc1 = make_float4(0.f, 0.f, 0.f, 0.f);
        for (int base = beg; base < end; base += 32) {
            int m = min(32, end - base);
            int2 ed = make_int2(0, 0);
            if (lane < m) ed = g_edges[base + lane];
            int j = 0;
            for (; j + 1 < m; j += 2) {
                int s0 = __shfl_sync(0xffffffffu, ed.x, j);
                float w0 = __int_as_float(__shfl_sync(0xffffffffu, ed.y, j));
                int s1 = __shfl_sync(0xffffffffu, ed.x, j + 1);
                float w1 = __int_as_float(__shfl_sync(0xffffffffu, ed.y, j + 1));
                uint2 r0 = *(const uint2*)(H + (size_t)s0 * D + 4 * lane);
                uint2 r1 = *(const uint2*)(H + (size_t)s1 * D + 4 * lane);
                float2 a01 = __half22float2(*(__half2*)&r0.x);
                float2 a23 = __half22float2(*(__half2*)&r0.y);
                float2 b01 = __half22float2(*(__half2*)&r1.x);
                float2 b23 = __half22float2(*(__half2*)&r1.y);
                acc0.x = fmaf(w0, a01.x, acc0.x);
                acc0.y = fmaf(w0, a01.y, acc0.y);
                acc0.z = fmaf(w0, a23.x, acc0.z);
                acc0.w = fmaf(w0, a23.y, acc0.w);
                acc1.x = fmaf(w1, b01.x, acc1.x);
                acc1.y = fmaf(w1, b01.y, acc1.y);
                acc1.z = fmaf(w1, b23.x, acc1.z);
                acc1.w = fmaf(w1, b23.y, acc1.w);
            }
            if (j < m) {
                int s0 = __shfl_sync(0xffffffffu, ed.x, j);
                float w0 = __int_as_float(__shfl_sync(0xffffffffu, ed.y, j));
                uint2 r0 = *(const uint2*)(H + (size_t)s0 * D + 4 * lane);
                float2 a01 = __half22float2(*(__half2*)&r0.x);
                float2 a23 = __half22float2(*(__half2*)&r0.y);
                acc0.x = fmaf(w0, a01.x, acc0.x);
                acc0.y = fmaf(w0, a01.y, acc0.y);
                acc0.z = fmaf(w0, a23.x, acc0.z);
                acc0.w = fmaf(w0, a23.y, acc0.w);
            }
        }
        float4 acc = make_float4(acc0.x + acc1.x, acc0.y + acc1.y,
                                 acc0.z + acc1.z, acc0.w + acc1.w);
        ((float4*)AGG)[(size_t)n * 32 + lane] = acc;
        cs.x += acc.x; cs.y += acc.y; cs.z += acc.z; cs.w += acc.w;
        cq.x = fmaf(acc.x, acc.x, cq.x);
        cq.y = fmaf(acc.y, acc.y, cq.y);
        cq.z = fmaf(acc.z, acc.z, cq.z);
        cq.w = fmaf(acc.w, acc.w, cq.w);
    }
    ssum[warp][lane] = cs;
    ssq[warp][lane] = cq;
    __syncthreads();
    if (warp == 0) {
#pragma unroll
        for (int i = 1; i < 8; i++) {
            float4 a = ssum[i][lane], b = ssq[i][lane];
            cs.x += a.x; cs.y += a.y; cs.z += a.z; cs.w += a.w;
            cq.x += b.x; cq.y += b.y; cq.z += b.z; cq.w += b.w;
        }
        float* ps = csbuf + 4 * lane;
        float* pq = cqbuf + 4 * lane;
        asm volatile("red.global.add.v4.f32 [%0], {%1,%2,%3,%4};"
                     :: "l"(ps), "f"(cs.x), "f"(cs.y), "f"(cs.z), "f"(cs.w) : "memory");
        asm volatile("red.global.add.v4.f32 [%0], {%1,%2,%3,%4};"
                     :: "l"(pq), "f"(cq.x), "f"(cq.y), "f"(cq.z), "f"(cq.w) : "memory");
    }
    // last block computes BN scale/shift
    if (threadIdx.x == 0) {
        __threadfence();
        s_last = (atomicAdd(&g_ctr[ctr_idx], 1) == (int)gridDim.x - 1) ? 1 : 0;
    }
    __syncthreads();
    if (s_last && threadIdx.x < D) {
        int c = threadIdx.x;
        float m = csbuf[c] * inv_n;
        float var = fmaf(-m, m, cqbuf[c] * inv_n);
        float inv = rsqrtf(var + BN_EPS);
        float sc = gamma[c] * inv;
        g_scale[c] = sc;
        g_shift[c] = fmaf(-sc, m, beta[c]);
    }
}

// ============================================================
// v[c] = sum_n deg[n] * relu(scale_c * agg[n,c] + shift_c),
// then last block computes out = v @ W2 + N*b2  (fused final)
// ============================================================
__global__ __launch_bounds__(256) void vreduce_final_kernel(
    const float* __restrict__ AGG, int nrows,
    const float* __restrict__ W2, const float* __restrict__ b2,
    float* __restrict__ out, float nf)
{
    __shared__ float4 ssum[8][32];
    __shared__ int s_last;
    const int kr = threadIdx.x & 31;
    const int rr = threadIdx.x >> 5;
    float4 sc4 = ((const float4*)g_scale)[kr];
    float4 sh4 = ((const float4*)g_shift)[kr];
    float4 acc = make_float4(0.f, 0.f, 0.f, 0.f);
    for (int n = blockIdx.x * 8 + rr; n < nrows; n += gridDim.x * 8) {
        float dn = g_deg[n];
        float4 a = ((const float4*)AGG)[(size_t)n * 32 + kr];
        float x0 = fmaxf(fmaf(sc4.x, a.x, sh4.x), 0.f);
        float x1 = fmaxf(fmaf(sc4.y, a.y, sh4.y), 0.f);
        float x2 = fmaxf(fmaf(sc4.z, a.z, sh4.z), 0.f);
        float x3 = fmaxf(fmaf(sc4.w, a.w, sh4.w), 0.f);
        acc.x = fmaf(dn, x0, acc.x);
        acc.y = fmaf(dn, x1, acc.y);
        acc.z = fmaf(dn, x2, acc.z);
        acc.w = fmaf(dn, x3, acc.w);
    }
    ssum[rr][kr] = acc;
    __syncthreads();
    if (rr == 0) {
#pragma unroll
        for (int i = 1; i < 8; i++) {
            float4 a = ssum[i][kr];
            acc.x += a.x; acc.y += a.y; acc.z += a.z; acc.w += a.w;
        }
        float* pv = &g_v[4 * kr];
        asm volatile("red.global.add.v4.f32 [%0], {%1,%2,%3,%4};"
                     :: "l"(pv), "f"(acc.x), "f"(acc.y), "f"(acc.z), "f"(acc.w) : "memory");
    }
    // last block: out[c] = sum_k v[k] * W2[k,c] + N*b2[c]
    if (threadIdx.x == 0) {
        __threadfence();
        s_last = (atomicAdd(&g_ctr[2], 1) == (int)gridDim.x - 1) ? 1 : 0;
    }
    __syncthreads();
    if (s_last && threadIdx.x < DOUT) {
        int c = threadIdx.x;
        float s = 0.f;
#pragma unroll 8
        for (int k = 0; k < D; k++) s = fmaf(g_v[k], W2[k * DOUT + c], s);
        out[c] = fmaf(nf, b2[c], s);
    }
}

// ============================================================

extern "C" void kernel_launch(void* const* d_in, const int* in_sizes, int n_in,
                              void* d_out, int out_size)
{
    const float* nf     = (const float*)d_in[0];
    const int*   ei     = (const int*)d_in[1];
    const float* ew     = (const float*)d_in[2];
    const float* W0     = (const float*)d_in[3];
    const float* W1     = (const float*)d_in[5];
    const float* W2     = (const float*)d_in[7];
    const float* b2     = (const float*)d_in[8];
    const float* gamma0 = (const float*)d_in[9];
    const float* beta0  = (const float*)d_in[10];
    const float* gamma1 = (const float*)d_in[11];
    const float* beta1  = (const float*)d_in[12];

    const int E = in_sizes[2];
    const int N = in_sizes[0] / D;
    const int* src = ei;
    const int* dst = ei + E;

    __half* p_h;
    float* p_agg;
    cudaGetSymbolAddress((void**)&p_h, g_h);
    cudaGetSymbolAddress((void**)&p_agg, g_agg);

    const size_t smem = (size_t)(2 * 128 * SMP) * sizeof(float);  // 135168 B
    cudaFuncSetAttribute((const void*)gemm_tc_kernel<false>,
                         cudaFuncAttributeMaxDynamicSharedMemorySize, (int)smem);
    cudaFuncSetAttribute((const void*)gemm_tc_kernel<true>,
                         cudaFuncAttributeMaxDynamicSharedMemorySize, (int)smem);

    const int gemm_blocks = (N + 127) / 128;
    const int stat_blocks = 1184;
    const int scan_blocks = (N + SCAN_CHUNK - 1) / SCAN_CHUNK;
    const int edge_blocks = (E + 255) / 256;
    const float inv_n = 1.0f / (float)N;

    // ---- init (single launch) ----
    init_kernel<<<(N + 255) / 256, 256>>>(N);

    // ---- CSR build (by dst) + weighted out-degree ----
    hist_deg_kernel<<<edge_blocks, 256>>>(src, dst, ew, E);
    scan1_kernel<<<scan_blocks, 256>>>(N);
    scan2_kernel<<<1, 128>>>(scan_blocks, N);
    scan3_kernel<<<scan_blocks, 256>>>(N);
    fill_kernel<<<edge_blocks, 256>>>(src, dst, ew, E);

    // ---- layer 0 ----
    gemm_tc_kernel<false><<<gemm_blocks, 256, smem>>>(nf, W0, p_h, N);
    gather_stats_kernel<<<stat_blocks, 256>>>(p_h, p_agg, N,
                                              gamma0, beta0, inv_n, 0);

    // ---- layer 1 ----
    gemm_tc_kernel<true><<<gemm_blocks, 256, smem>>>(p_agg, W1, p_h, N);
    gather_stats_kernel<<<stat_blocks, 256>>>(p_h, p_agg, N,
                                              gamma1, beta1, inv_n, 1);

    // ---- layer 2 collapsed algebraically (vreduce + final fused) ----
    vreduce_final_kernel<<<stat_blocks, 256>>>(p_agg, N, W2, b2,
                                               (float*)d_out, (float)N);
}